// round 3
// baseline (speedup 1.0000x reference)
#include <cuda_runtime.h>
#include <cuda_bf16.h>
#include <cstdint>
#include <cstddef>

#define BN 32
#define LN 2048
#define TN 2047          // number of key timesteps (L-1)
#define HN 512
#define CC 32            // chunk size
#define NCH 64
#define EPSV 1e-6f
#define GP 33            // padded 32x32 stride

// Static device scratch
__device__ float g_Tinv[BN * NCH * CC * CC];   // 8 MB
__device__ float g_beta[BN * NCH * CC];
__device__ float g_ctx[BN * HN];
__device__ int   g_flag[BN * NCH];

__device__ __forceinline__ float warp_sum(float v) {
    v += __shfl_xor_sync(0xffffffffu, v, 16);
    v += __shfl_xor_sync(0xffffffffu, v, 8);
    v += __shfl_xor_sync(0xffffffffu, v, 4);
    v += __shfl_xor_sync(0xffffffffu, v, 2);
    v += __shfl_xor_sync(0xffffffffu, v, 1);
    return v;
}

__device__ __forceinline__ void cp16(void* smem_dst, const void* gsrc) {
    unsigned sa = (unsigned)__cvta_generic_to_shared(smem_dst);
    asm volatile("cp.async.ca.shared.global [%0], [%1], 16;" :: "r"(sa), "l"(gsrc));
}
__device__ __forceinline__ void cp_commit() { asm volatile("cp.async.commit_group;"); }
__device__ __forceinline__ void cp_wait0()  { asm volatile("cp.async.wait_group 0;" ::: "memory"); }

__global__ void init_kernel() {
    int i = blockIdx.x * 1024 + threadIdx.x;
    if (i < BN * NCH) g_flag[i] = 0;
}

// ---------------------------------------------------------------------------
// Phase A: per (b, chunk): reversed-row Gram (outer-product, no shuffles),
// betas, Tinv via nilpotent doubling. grid (BN, NCH) with c reversed so
// chunk 63 (consumed first by scan) is produced first.
// ---------------------------------------------------------------------------
__global__ void __launch_bounds__(256) gram_kernel(const float* __restrict__ hidden) {
    extern __shared__ float sm[];
    float* Ks    = sm;                 // [CC][HN]  reversed-time rows (float4 laid out)
    float* G     = Ks + CC * HN;       // [32][33]
    float* Ma    = G  + CC * GP;       // doubling buffers
    float* Mb    = Ma + CC * GP;
    float* Xs    = Mb + CC * GP;
    float* Ps    = Xs + CC * GP;
    float* betas = Ps + CC * GP;       // [32]

    const int b = blockIdx.x;
    const int c = NCH - 1 - blockIdx.y;
    const int tid = threadIdx.x;

    // Zero G (accumulated via smem atomics)
    for (int e = tid; e < CC * GP; e += 256) G[e] = 0.f;

    // Load chunk rows, reversed in time; pad t >= TN with zeros.
    float4* Ks4 = reinterpret_cast<float4*>(Ks);
    for (int idx = tid; idx < CC * (HN / 4); idx += 256) {
        int row = idx >> 7;
        int col4 = idx & 127;
        int t = c * CC + (CC - 1) - row;
        float4 v = make_float4(0.f, 0.f, 0.f, 0.f);
        if (t < TN)
            v = *reinterpret_cast<const float4*>(hidden + (size_t)(b * LN + t) * HN + col4 * 4);
        Ks4[row * 128 + col4] = v;
    }
    __syncthreads();

    // Outer-product Gram: 4 h-groups x 64 output-threads, 4x4 tile each.
    {
        const int g  = tid >> 6;          // h-group 0..3
        const int tr = tid & 63;
        const int i4 = tr >> 3, j4 = tr & 7;
        const float4* A4 = Ks4 + (4 * i4) * 128;
        const float4* B4 = Ks4 + (4 * j4) * 128;

        float acc[4][4];
        #pragma unroll
        for (int i = 0; i < 4; i++)
            #pragma unroll
            for (int j = 0; j < 4; j++) acc[i][j] = 0.f;

        for (int h4 = g * 32; h4 < g * 32 + 32; h4++) {
            float4 av[4], bv[4];
            #pragma unroll
            for (int i = 0; i < 4; i++) av[i] = A4[i * 128 + h4];
            #pragma unroll
            for (int j = 0; j < 4; j++) bv[j] = B4[j * 128 + h4];
            #pragma unroll
            for (int i = 0; i < 4; i++)
                #pragma unroll
                for (int j = 0; j < 4; j++)
                    acc[i][j] += av[i].x * bv[j].x + av[i].y * bv[j].y +
                                 av[i].z * bv[j].z + av[i].w * bv[j].w;
        }
        #pragma unroll
        for (int i = 0; i < 4; i++)
            #pragma unroll
            for (int j = 0; j < 4; j++)
                atomicAdd(&G[(4 * i4 + i) * GP + (4 * j4 + j)], acc[i][j]);
    }
    __syncthreads();

    if (tid < CC) {
        float bt = 1.0f / (G[tid * GP + tid] + EPSV);
        betas[tid] = bt;
        g_beta[(b * NCH + c) * CC + tid] = bt;
    }
    __syncthreads();

    // M = L (strictly lower, L_ij = beta_j * G_ij), X = I - L
    for (int e = tid; e < CC * CC; e += 256) {
        int i = e >> 5, j = e & 31;
        float v = (j < i) ? G[i * GP + j] * betas[j] : 0.f;
        Ma[i * GP + j] = v;
        Xs[i * GP + j] = ((i == j) ? 1.f : 0.f) - v;
    }
    __syncthreads();

    // (I+L)^-1 = (I-L)(I+L^2)(I+L^4)(I+L^8)(I+L^16); L^32 = 0.
    float* Mc = Ma;
    float* Mn = Mb;
    for (int p = 1; p <= 8; p <<= 1) {
        // T = Mc*Mc  (= L^{2p}; nonzero only i-j >= 2p; k in [j+p, i-p])
        for (int e = tid; e < CC * CC; e += 256) {
            int i = e >> 5, j = e & 31;
            float s = 0.f;
            for (int k = j + p; k <= i - p; k++)
                s += Mc[i * GP + k] * Mc[k * GP + j];
            Mn[i * GP + j] = s;
        }
        __syncthreads();
        // P = X * T  (k in [j+2p, i])
        for (int e = tid; e < CC * CC; e += 256) {
            int i = e >> 5, j = e & 31;
            float s = 0.f;
            for (int k = j + 2 * p; k <= i; k++)
                s += Xs[i * GP + k] * Mn[k * GP + j];
            Ps[i * GP + j] = s;
        }
        __syncthreads();
        for (int e = tid; e < CC * CC; e += 256) {
            int i = e >> 5, j = e & 31;
            Xs[i * GP + j] += Ps[i * GP + j];
        }
        __syncthreads();
        float* t = Mc; Mc = Mn; Mn = t;
    }

    // Write Tinv, release flag
    float* Tout = g_Tinv + (size_t)(b * NCH + c) * CC * CC;
    for (int e = tid; e < CC * CC; e += 256) {
        int i = e >> 5, j = e & 31;
        Tout[i * CC + j] = Xs[i * GP + j];
    }
    __threadfence();
    __syncthreads();
    if (tid == 0) atomicExch(&g_flag[b * NCH + c], 1);
}

// ---------------------------------------------------------------------------
// Phase B: backward chunked scan, runs CONCURRENTLY with gram (flag-gated).
// grid BN, 512 threads, double-buffered cp.async.
// ---------------------------------------------------------------------------
__global__ void __launch_bounds__(512) scan_kernel(const float* __restrict__ hidden) {
    extern __shared__ float sm[];
    float* Kb  = sm;                       // 2 * CC * HN
    float* Tb  = sm + 2 * CC * HN;         // 2 * CC * CC
    float* btb = Tb + 2 * CC * CC;         // 2 * CC
    float* us  = btb + 2 * CC;             // HN
    float* ms  = us + HN;                  // CC
    float* ss  = ms + CC;                  // CC
    float* sbs = ss + CC;                  // CC

    const int b = blockIdx.x;
    const int tid = threadIdx.x, wid = tid >> 5, lane = tid & 31;

    us[tid] = hidden[(size_t)(b * LN + (LN - 1)) * HN + tid];
    float racc = 0.f;

    const float* hb_base = hidden + (size_t)b * LN * HN;

    auto prefetch = [&](int c, int buf) {
        // wait for gram to publish this chunk's Tinv/beta
        if (tid == 0) {
            while (atomicAdd(&g_flag[b * NCH + c], 0) == 0) {}
            __threadfence();
        }
        __syncthreads();
        float* dstK = Kb + buf * (CC * HN);
        for (int idx = tid; idx < CC * (HN / 4); idx += 512) {
            int row = idx >> 7, col4 = idx & 127;
            int t = c * CC + (CC - 1) - row;
            float* dp = dstK + row * HN + col4 * 4;
            if (t < TN) cp16(dp, hb_base + (size_t)t * HN + col4 * 4);
            else *reinterpret_cast<float4*>(dp) = make_float4(0.f, 0.f, 0.f, 0.f);
        }
        const float* Tsrc = g_Tinv + (size_t)(b * NCH + c) * CC * CC;
        float* Tdst = Tb + buf * (CC * CC);
        for (int idx = tid; idx < CC * CC / 4; idx += 512)
            cp16(Tdst + idx * 4, Tsrc + idx * 4);
        if (tid < CC / 4)
            cp16(btb + buf * CC + tid * 4, g_beta + (size_t)(b * NCH + c) * CC + tid * 4);
        cp_commit();
    };

    prefetch(NCH - 1, (NCH - 1) & 1);

    for (int c = NCH - 1; c >= 0; c--) {
        const int buf = c & 1;
        cp_wait0();
        __syncthreads();
        if (c > 0) prefetch(c - 1, buf ^ 1);

        const float* K  = Kb + buf * (CC * HN);
        const float* Ti = Tb + buf * (CC * CC);
        const float* bt = btb + buf * CC;

        // m_j = K_j . u  (warp -> rows wid, wid+16)
        {
            const float4* K4 = reinterpret_cast<const float4*>(K);
            const float4* u4 = reinterpret_cast<const float4*>(us);
            int r0 = wid, r1 = wid + 16;
            float a0 = 0.f, a1 = 0.f;
            #pragma unroll
            for (int stp = 0; stp < 4; stp++) {
                int hb = stp * 32 + lane;
                float4 uv = u4[hb];
                float4 k0 = K4[r0 * 128 + hb];
                float4 k1 = K4[r1 * 128 + hb];
                a0 += k0.x * uv.x + k0.y * uv.y + k0.z * uv.z + k0.w * uv.w;
                a1 += k1.x * uv.x + k1.y * uv.y + k1.z * uv.z + k1.w * uv.w;
            }
            a0 = warp_sum(a0);
            a1 = warp_sum(a1);
            if (lane == 0) { ms[r0] = a0; ms[r1] = a1; }
        }
        __syncthreads();

        // s = Tinv * m ; sb = beta .* s
        {
            int r0 = wid, r1 = wid + 16;
            float mv = ms[lane];
            float a0 = Ti[r0 * CC + lane] * mv;
            float a1 = Ti[r1 * CC + lane] * mv;
            a0 = warp_sum(a0);
            a1 = warp_sum(a1);
            if (lane == 0) {
                ss[r0] = a0; sbs[r0] = a0 * bt[r0];
                ss[r1] = a1; sbs[r1] = a1 * bt[r1];
            }
        }
        __syncthreads();

        // u -= K^T sb ; ctx += K^T s
        {
            float ua = us[tid];
            #pragma unroll
            for (int j = 0; j < CC; j++) {
                float kv = K[j * HN + tid];
                ua   -= kv * sbs[j];
                racc += kv * ss[j];
            }
            us[tid] = ua;
        }
        __syncthreads();
    }
    g_ctx[b * HN + tid] = racc;
}

// ---------------------------------------------------------------------------
// Phase C: out[b,i] = ctx[b,:] . W[i,:] + bias[i].
// ---------------------------------------------------------------------------
__global__ void __launch_bounds__(256) out_kernel(const float* __restrict__ W,
                                                  const float* __restrict__ bias,
                                                  float* __restrict__ out) {
    __shared__ float cs[HN];
    const int b = blockIdx.x;
    for (int i = threadIdx.x; i < HN; i += 256) cs[i] = g_ctx[b * HN + i];
    __syncthreads();
    const int wid = threadIdx.x >> 5, lane = threadIdx.x & 31;
    const float4* c4 = reinterpret_cast<const float4*>(cs);
    for (int i = wid * 64; i < wid * 64 + 64; i++) {
        const float4* w4 = reinterpret_cast<const float4*>(W + (size_t)i * HN);
        float acc = 0.f;
        #pragma unroll
        for (int stp = 0; stp < 4; stp++) {
            float4 wv = w4[stp * 32 + lane];
            float4 cv = c4[stp * 32 + lane];
            acc += wv.x * cv.x + wv.y * cv.y + wv.z * cv.z + wv.w * cv.w;
        }
        acc = warp_sum(acc);
        if (lane == 0) out[b * HN + i] = acc + bias[i];
    }
}

extern "C" void kernel_launch(void* const* d_in, const int* in_sizes, int n_in,
                              void* d_out, int out_size) {
    const float* hidden = (const float*)d_in[0];
    const float* W      = (const float*)d_in[1];
    const float* bias   = (const float*)d_in[2];
    float* out          = (float*)d_out;

    const int smA = (CC * HN + 5 * CC * GP + CC) * (int)sizeof(float);              // ~87 KB
    const int smB = (2 * CC * HN + 2 * CC * CC + 2 * CC + HN + 3 * CC)
                    * (int)sizeof(float);                                            // ~142 KB

    static cudaStream_t s2 = nullptr;
    static cudaEvent_t evA = nullptr, evB = nullptr;
    if (!s2) {
        cudaStreamCreateWithFlags(&s2, cudaStreamNonBlocking);
        cudaEventCreateWithFlags(&evA, cudaEventDisableTiming);
        cudaEventCreateWithFlags(&evB, cudaEventDisableTiming);
        cudaFuncSetAttribute(gram_kernel, cudaFuncAttributeMaxDynamicSharedMemorySize, smA);
        cudaFuncSetAttribute(scan_kernel, cudaFuncAttributeMaxDynamicSharedMemorySize, smB);
    }

    // init flags, then fork: scan on s2 (flag-gated), gram on main stream.
    init_kernel<<<2, 1024>>>();
    cudaEventRecord(evA, 0);
    cudaStreamWaitEvent(s2, evA, 0);
    scan_kernel<<<BN, 512, smB, s2>>>(hidden);
    gram_kernel<<<dim3(BN, NCH), 256, smA>>>(hidden);
    cudaEventRecord(evB, s2);
    cudaStreamWaitEvent(0, evB, 0);
    out_kernel<<<BN, 256>>>(W, bias, out);
}

// round 4
// speedup vs baseline: 2.5965x; 2.5965x over previous
#include <cuda_runtime.h>
#include <cuda_bf16.h>
#include <cstdint>
#include <cstddef>

#define BN 32
#define LN 2048
#define TN 2047          // number of key timesteps (L-1)
#define HN 512
#define CC 32            // chunk size
#define NCH 64
#define EPSV 1e-6f
#define GP 33            // padded 32x32 stride

// Static device scratch
__device__ float g_Tinv[BN * NCH * CC * CC];   // 8 MB
__device__ float g_beta[BN * NCH * CC];
__device__ float g_ctx[BN * HN];
__device__ int   g_flag[BN * NCH];

__device__ __forceinline__ float warp_sum(float v) {
    v += __shfl_xor_sync(0xffffffffu, v, 16);
    v += __shfl_xor_sync(0xffffffffu, v, 8);
    v += __shfl_xor_sync(0xffffffffu, v, 4);
    v += __shfl_xor_sync(0xffffffffu, v, 2);
    v += __shfl_xor_sync(0xffffffffu, v, 1);
    return v;
}

// L1-bypassing 16B async copy (data is consumed from smem, L1 copy is waste)
__device__ __forceinline__ void cp16cg(void* smem_dst, const void* gsrc) {
    unsigned sa = (unsigned)__cvta_generic_to_shared(smem_dst);
    asm volatile("cp.async.cg.shared.global [%0], [%1], 16;" :: "r"(sa), "l"(gsrc));
}
__device__ __forceinline__ void cp_commit() { asm volatile("cp.async.commit_group;"); }
__device__ __forceinline__ void cp_wait0()  { asm volatile("cp.async.wait_group 0;" ::: "memory"); }

__global__ void init_kernel() {
    int i = blockIdx.x * 1024 + threadIdx.x;
    if (i < BN * NCH) g_flag[i] = 0;
}

// ---------------------------------------------------------------------------
// Phase A (R2 algorithm + cp.async.cg load + flag release):
// per (b, chunk): reversed-row Gram, betas, Tinv = (I+L)^-1.
// grid (BN, NCH), y reversed so chunk 63 (consumed first) is produced first.
// ---------------------------------------------------------------------------
__global__ void __launch_bounds__(256) gram_kernel(const float* __restrict__ hidden) {
    extern __shared__ float sm[];
    float* Ks    = sm;                 // [CC][HN]  reversed-time rows
    float* G     = sm + CC * HN;       // [CC][GP]  lower triangle
    float* betas = G + CC * GP;        // [CC]

    const int b = blockIdx.x;
    const int c = NCH - 1 - blockIdx.y;
    const int tid = threadIdx.x, wid = tid >> 5, lane = tid & 31;

    float4* Ks4 = reinterpret_cast<float4*>(Ks);
    for (int idx = tid; idx < CC * (HN / 4); idx += 256) {
        int row = idx >> 7;
        int col4 = idx & 127;
        int t = c * CC + (CC - 1) - row;
        if (t < TN)
            cp16cg(Ks4 + row * 128 + col4,
                   hidden + (size_t)(b * LN + t) * HN + col4 * 4);
        else
            Ks4[row * 128 + col4] = make_float4(0.f, 0.f, 0.f, 0.f);
    }
    cp_commit();
    cp_wait0();
    __syncthreads();

    // Lower-triangular Gram: 36 4x4 blocks across 8 warps (R2 scheme).
    for (int blk = wid; blk < 36; blk += 8) {
        int BI = 0, rem = blk;
        while (rem > BI) { BI++; rem -= BI; }
        int BJ = rem;

        float acc[4][4];
        #pragma unroll
        for (int i = 0; i < 4; i++)
            #pragma unroll
            for (int j = 0; j < 4; j++) acc[i][j] = 0.f;

        const float4* A4 = Ks4 + (4 * BI) * 128;
        const float4* B4 = Ks4 + (4 * BJ) * 128;
        #pragma unroll
        for (int stp = 0; stp < 4; stp++) {
            int hb = stp * 32 + lane;
            float4 av[4], bv[4];
            #pragma unroll
            for (int i = 0; i < 4; i++) av[i] = A4[i * 128 + hb];
            #pragma unroll
            for (int j = 0; j < 4; j++) bv[j] = B4[j * 128 + hb];
            #pragma unroll
            for (int i = 0; i < 4; i++)
                #pragma unroll
                for (int j = 0; j < 4; j++)
                    acc[i][j] += av[i].x * bv[j].x + av[i].y * bv[j].y +
                                 av[i].z * bv[j].z + av[i].w * bv[j].w;
        }
        #pragma unroll
        for (int i = 0; i < 4; i++)
            #pragma unroll
            for (int j = 0; j < 4; j++) {
                float v = warp_sum(acc[i][j]);
                if (lane == i * 4 + j) G[(4 * BI + i) * GP + (4 * BJ + j)] = v;
            }
    }
    __syncthreads();

    if (tid < CC) {
        float bt = 1.0f / (G[tid * GP + tid] + EPSV);
        betas[tid] = bt;
        g_beta[(b * NCH + c) * CC + tid] = bt;
    }
    __syncthreads();

    // Unit-lower-triangular inverse: column per lane (warp 0), then release.
    if (wid == 0) {
        float* xs = Ks;  // reuse as [CC][GP]
        float* Tout = g_Tinv + (size_t)(b * NCH + c) * CC * CC;
        float x0 = (lane == 0) ? 1.f : 0.f;
        xs[lane] = x0;
        Tout[lane] = x0;
        for (int i = 1; i < CC; i++) {
            float acc = 0.f;
            for (int j = 0; j < i; j++)
                acc -= (G[i * GP + j] * betas[j]) * xs[j * GP + lane];
            float xi = (i > lane) ? acc : ((i == lane) ? 1.f : 0.f);
            xs[i * GP + lane] = xi;
            Tout[i * CC + lane] = xi;
        }
        __syncwarp();
        __threadfence();
        if (lane == 0) atomicExch(&g_flag[b * NCH + c], 1);
    }
}

// ---------------------------------------------------------------------------
// Phase B: backward chunked scan, runs CONCURRENTLY with gram.
// K prefetch is flag-free and issued BEFORE compute; the flag is only awaited
// AFTER the current chunk's compute, to fetch Tinv/beta of the next chunk.
// grid BN, 512 threads, double-buffered cp.async.
// ---------------------------------------------------------------------------
__global__ void __launch_bounds__(512) scan_kernel(const float* __restrict__ hidden) {
    extern __shared__ float sm[];
    float* Kb  = sm;                       // 2 * CC * HN
    float* Tb  = sm + 2 * CC * HN;         // 2 * CC * CC
    float* btb = Tb + 2 * CC * CC;         // 2 * CC
    float* us  = btb + 2 * CC;             // HN
    float* ms  = us + HN;                  // CC
    float* ss  = ms + CC;                  // CC
    float* sbs = ss + CC;                  // CC

    const int b = blockIdx.x;
    const int tid = threadIdx.x, wid = tid >> 5, lane = tid & 31;

    us[tid] = hidden[(size_t)(b * LN + (LN - 1)) * HN + tid];
    float racc = 0.f;

    const float* hb_base = hidden + (size_t)b * LN * HN;

    auto prefetch_K = [&](int c, int buf) {
        float* dstK = Kb + buf * (CC * HN);
        for (int idx = tid; idx < CC * (HN / 4); idx += 512) {
            int row = idx >> 7, col4 = idx & 127;
            int t = c * CC + (CC - 1) - row;
            float* dp = dstK + row * HN + col4 * 4;
            if (t < TN) cp16cg(dp, hb_base + (size_t)t * HN + col4 * 4);
            else *reinterpret_cast<float4*>(dp) = make_float4(0.f, 0.f, 0.f, 0.f);
        }
    };
    auto wait_flag = [&](int c) {
        if (tid == 0) {
            while (atomicAdd(&g_flag[b * NCH + c], 0) == 0) __nanosleep(64);
            __threadfence();
        }
        __syncthreads();
    };
    auto prefetch_T = [&](int c, int buf) {
        const float* Tsrc = g_Tinv + (size_t)(b * NCH + c) * CC * CC;
        float* Tdst = Tb + buf * (CC * CC);
        for (int idx = tid; idx < CC * CC / 4; idx += 512)
            cp16cg(Tdst + idx * 4, Tsrc + idx * 4);
        if (tid < CC / 4)
            cp16cg(btb + buf * CC + tid * 4, g_beta + (size_t)(b * NCH + c) * CC + tid * 4);
    };

    // initial fill for chunk NCH-1
    prefetch_K(NCH - 1, (NCH - 1) & 1);
    wait_flag(NCH - 1);
    prefetch_T(NCH - 1, (NCH - 1) & 1);
    cp_commit();

    for (int c = NCH - 1; c >= 0; c--) {
        const int buf = c & 1;
        cp_wait0();
        __syncthreads();

        // issue flag-free K prefetch for the next chunk immediately
        if (c > 0) prefetch_K(c - 1, buf ^ 1);

        const float* K  = Kb + buf * (CC * HN);
        const float* Ti = Tb + buf * (CC * CC);
        const float* bt = btb + buf * CC;

        // step 1: m_j = K_j . u  (warp -> rows wid, wid+16)
        {
            const float4* K4 = reinterpret_cast<const float4*>(K);
            const float4* u4 = reinterpret_cast<const float4*>(us);
            int r0 = wid, r1 = wid + 16;
            float a0 = 0.f, a1 = 0.f;
            #pragma unroll
            for (int stp = 0; stp < 4; stp++) {
                int hb = stp * 32 + lane;
                float4 uv = u4[hb];
                float4 k0 = K4[r0 * 128 + hb];
                float4 k1 = K4[r1 * 128 + hb];
                a0 += k0.x * uv.x + k0.y * uv.y + k0.z * uv.z + k0.w * uv.w;
                a1 += k1.x * uv.x + k1.y * uv.y + k1.z * uv.z + k1.w * uv.w;
            }
            a0 = warp_sum(a0);
            a1 = warp_sum(a1);
            if (lane == 0) { ms[r0] = a0; ms[r1] = a1; }
        }
        __syncthreads();

        // step 2: s = Tinv * m ; sb = beta .* s
        {
            int r0 = wid, r1 = wid + 16;
            float mv = ms[lane];
            float a0 = Ti[r0 * CC + lane] * mv;
            float a1 = Ti[r1 * CC + lane] * mv;
            a0 = warp_sum(a0);
            a1 = warp_sum(a1);
            if (lane == 0) {
                ss[r0] = a0; sbs[r0] = a0 * bt[r0];
                ss[r1] = a1; sbs[r1] = a1 * bt[r1];
            }
        }
        __syncthreads();

        // step 3: u -= K^T sb ; ctx += K^T s
        {
            float ua = us[tid];
            #pragma unroll
            for (int j = 0; j < CC; j++) {
                float kv = K[j * HN + tid];
                ua   -= kv * sbs[j];
                racc += kv * ss[j];
            }
            us[tid] = ua;
        }
        __syncthreads();

        // only NOW gate on the producer, for the next chunk's Tinv/beta
        if (c > 0) {
            wait_flag(c - 1);
            prefetch_T(c - 1, buf ^ 1);
            cp_commit();
        }
    }
    g_ctx[b * HN + tid] = racc;
}

// ---------------------------------------------------------------------------
// Phase C: out[b,i] = ctx[b,:] . W[i,:] + bias[i].
// grid (BN, 8), 256 threads; each warp does 8 rows with 8-way load MLP.
// ---------------------------------------------------------------------------
__global__ void __launch_bounds__(256) out_kernel(const float* __restrict__ W,
                                                  const float* __restrict__ bias,
                                                  float* __restrict__ out) {
    __shared__ float cs[HN];
    const int b = blockIdx.x;
    for (int i = threadIdx.x; i < HN; i += 256) cs[i] = g_ctx[b * HN + i];
    __syncthreads();

    const int wid = threadIdx.x >> 5, lane = threadIdx.x & 31;
    const int row0 = blockIdx.y * 64 + wid * 8;
    const float4* c4 = reinterpret_cast<const float4*>(cs);

    float acc[8];
    #pragma unroll
    for (int r = 0; r < 8; r++) acc[r] = 0.f;

    #pragma unroll
    for (int stp = 0; stp < 4; stp++) {
        int hb = stp * 32 + lane;
        float4 cv = c4[hb];
        #pragma unroll
        for (int r = 0; r < 8; r++) {
            float4 wv = reinterpret_cast<const float4*>(W + (size_t)(row0 + r) * HN)[hb];
            acc[r] += wv.x * cv.x + wv.y * cv.y + wv.z * cv.z + wv.w * cv.w;
        }
    }
    #pragma unroll
    for (int r = 0; r < 8; r++) {
        float v = warp_sum(acc[r]);
        if (lane == 0) out[b * HN + row0 + r] = v + bias[row0 + r];
    }
}

extern "C" void kernel_launch(void* const* d_in, const int* in_sizes, int n_in,
                              void* d_out, int out_size) {
    const float* hidden = (const float*)d_in[0];
    const float* W      = (const float*)d_in[1];
    const float* bias   = (const float*)d_in[2];
    float* out          = (float*)d_out;

    const int smA = (CC * HN + CC * GP + CC) * (int)sizeof(float);                  // ~68 KB
    const int smB = (2 * CC * HN + 2 * CC * CC + 2 * CC + HN + 3 * CC)
                    * (int)sizeof(float);                                            // ~139 KB

    static cudaStream_t s2 = nullptr;
    static cudaEvent_t evA = nullptr, evB = nullptr;
    if (!s2) {
        cudaStreamCreateWithFlags(&s2, cudaStreamNonBlocking);
        cudaEventCreateWithFlags(&evA, cudaEventDisableTiming);
        cudaEventCreateWithFlags(&evB, cudaEventDisableTiming);
        cudaFuncSetAttribute(gram_kernel, cudaFuncAttributeMaxDynamicSharedMemorySize, smA);
        cudaFuncSetAttribute(scan_kernel, cudaFuncAttributeMaxDynamicSharedMemorySize, smB);
    }

    // init flags, then fork: scan on s2 (flag-gated per chunk), gram on main.
    init_kernel<<<2, 1024>>>();
    cudaEventRecord(evA, 0);
    cudaStreamWaitEvent(s2, evA, 0);
    scan_kernel<<<BN, 512, smB, s2>>>(hidden);
    gram_kernel<<<dim3(BN, NCH), 256, smA>>>(hidden);
    cudaEventRecord(evB, s2);
    cudaStreamWaitEvent(0, evB, 0);
    out_kernel<<<dim3(BN, 8), 256>>>(W, bias, out);
}

// round 5
// speedup vs baseline: 2.6156x; 1.0073x over previous
#include <cuda_runtime.h>
#include <cuda_bf16.h>
#include <cstdint>
#include <cstddef>

#define BN 32
#define LN 2048
#define TN 2047          // number of key timesteps (L-1)
#define HN 512
#define CC 32            // chunk size
#define NCH 64
#define EPSV 1e-6f
#define GP 33            // padded 32x32 stride
#define SCAN_PAD 6144    // smem pad to evict gram CTAs from scan SMs

// Static device scratch
__device__ float g_Tinv[BN * NCH * CC * CC];   // 8 MB
__device__ float g_beta[BN * NCH * CC];
__device__ float g_ctx[BN * HN];
__device__ int   g_flag[BN * NCH];

__device__ __forceinline__ float warp_sum(float v) {
    v += __shfl_xor_sync(0xffffffffu, v, 16);
    v += __shfl_xor_sync(0xffffffffu, v, 8);
    v += __shfl_xor_sync(0xffffffffu, v, 4);
    v += __shfl_xor_sync(0xffffffffu, v, 2);
    v += __shfl_xor_sync(0xffffffffu, v, 1);
    return v;
}

// L1-bypassing 16B async copy
__device__ __forceinline__ void cp16cg(void* smem_dst, const void* gsrc) {
    unsigned sa = (unsigned)__cvta_generic_to_shared(smem_dst);
    asm volatile("cp.async.cg.shared.global [%0], [%1], 16;" :: "r"(sa), "l"(gsrc));
}
__device__ __forceinline__ void cp_commit() { asm volatile("cp.async.commit_group;"); }
__device__ __forceinline__ void cp_wait0()  { asm volatile("cp.async.wait_group 0;" ::: "memory"); }

__global__ void init_kernel() {
    int i = blockIdx.x * 1024 + threadIdx.x;
    if (i < BN * NCH) g_flag[i] = 0;
}

// ---------------------------------------------------------------------------
// Phase A: per (b, chunk): reversed-row Gram, betas, Tinv = (I+L)^-1.
// grid (BN, NCH), y reversed so chunk 63 (consumed first) is produced first.
// ---------------------------------------------------------------------------
__global__ void __launch_bounds__(256) gram_kernel(const float* __restrict__ hidden) {
    extern __shared__ float sm[];
    float* Ks    = sm;                 // [CC][HN]  reversed-time rows
    float* G     = sm + CC * HN;       // [CC][GP]  lower triangle
    float* betas = G + CC * GP;        // [CC]

    const int b = blockIdx.x;
    const int c = NCH - 1 - blockIdx.y;
    const int tid = threadIdx.x, wid = tid >> 5, lane = tid & 31;

    float4* Ks4 = reinterpret_cast<float4*>(Ks);
    for (int idx = tid; idx < CC * (HN / 4); idx += 256) {
        int row = idx >> 7;
        int col4 = idx & 127;
        int t = c * CC + (CC - 1) - row;
        if (t < TN)
            cp16cg(Ks4 + row * 128 + col4,
                   hidden + (size_t)(b * LN + t) * HN + col4 * 4);
        else
            Ks4[row * 128 + col4] = make_float4(0.f, 0.f, 0.f, 0.f);
    }
    cp_commit();
    cp_wait0();
    __syncthreads();

    // Lower-triangular Gram: 36 4x4 blocks across 8 warps.
    for (int blk = wid; blk < 36; blk += 8) {
        int BI = 0, rem = blk;
        while (rem > BI) { BI++; rem -= BI; }
        int BJ = rem;

        float acc[4][4];
        #pragma unroll
        for (int i = 0; i < 4; i++)
            #pragma unroll
            for (int j = 0; j < 4; j++) acc[i][j] = 0.f;

        const float4* A4 = Ks4 + (4 * BI) * 128;
        const float4* B4 = Ks4 + (4 * BJ) * 128;
        #pragma unroll
        for (int stp = 0; stp < 4; stp++) {
            int hb = stp * 32 + lane;
            float4 av[4], bv[4];
            #pragma unroll
            for (int i = 0; i < 4; i++) av[i] = A4[i * 128 + hb];
            #pragma unroll
            for (int j = 0; j < 4; j++) bv[j] = B4[j * 128 + hb];
            #pragma unroll
            for (int i = 0; i < 4; i++)
                #pragma unroll
                for (int j = 0; j < 4; j++)
                    acc[i][j] += av[i].x * bv[j].x + av[i].y * bv[j].y +
                                 av[i].z * bv[j].z + av[i].w * bv[j].w;
        }
        #pragma unroll
        for (int i = 0; i < 4; i++)
            #pragma unroll
            for (int j = 0; j < 4; j++) {
                float v = warp_sum(acc[i][j]);
                if (lane == i * 4 + j) G[(4 * BI + i) * GP + (4 * BJ + j)] = v;
            }
    }
    __syncthreads();

    // Warp 0 finishes alone: betas + inversion + release (other warps exit).
    if (wid == 0) {
        float bt = 1.0f / (G[lane * GP + lane] + EPSV);
        betas[lane] = bt;
        g_beta[(b * NCH + c) * CC + lane] = bt;
        __syncwarp();

        float* xs = Ks;  // reuse as [CC][GP]
        float* Tout = g_Tinv + (size_t)(b * NCH + c) * CC * CC;
        float x0 = (lane == 0) ? 1.f : 0.f;
        xs[lane] = x0;
        Tout[lane] = x0;
        for (int i = 1; i < CC; i++) {
            float acc = 0.f;
            for (int j = 0; j < i; j++)
                acc -= (G[i * GP + j] * betas[j]) * xs[j * GP + lane];
            float xi = (i > lane) ? acc : ((i == lane) ? 1.f : 0.f);
            xs[i * GP + lane] = xi;
            Tout[i * CC + lane] = xi;
        }
        __syncwarp();
        __threadfence();
        if (lane == 0) atomicExch(&g_flag[b * NCH + c], 1);
    }
}

// ---------------------------------------------------------------------------
// Phase B: backward chunked scan, concurrent with gram (flag-gated late).
// smem padded so no gram CTA fits on scan SMs. grid BN, 512 threads.
// ---------------------------------------------------------------------------
__global__ void __launch_bounds__(512) scan_kernel(const float* __restrict__ hidden) {
    extern __shared__ float sm[];
    float* Kb  = sm;                       // 2 * CC * HN
    float* Tb  = sm + 2 * CC * HN;         // 2 * CC * CC
    float* btb = Tb + 2 * CC * CC;         // 2 * CC
    float* us  = btb + 2 * CC;             // HN
    float* ms  = us + HN;                  // CC
    float* ss  = ms + CC;                  // CC
    float* sbs = ss + CC;                  // CC

    const int b = blockIdx.x;
    const int tid = threadIdx.x, wid = tid >> 5, lane = tid & 31;

    us[tid] = hidden[(size_t)(b * LN + (LN - 1)) * HN + tid];
    float racc = 0.f;

    const float* hb_base = hidden + (size_t)b * LN * HN;

    auto prefetch_K = [&](int c, int buf) {
        float* dstK = Kb + buf * (CC * HN);
        for (int idx = tid; idx < CC * (HN / 4); idx += 512) {
            int row = idx >> 7, col4 = idx & 127;
            int t = c * CC + (CC - 1) - row;
            float* dp = dstK + row * HN + col4 * 4;
            if (t < TN) cp16cg(dp, hb_base + (size_t)t * HN + col4 * 4);
            else *reinterpret_cast<float4*>(dp) = make_float4(0.f, 0.f, 0.f, 0.f);
        }
    };
    auto wait_flag = [&](int c) {
        if (tid == 0) {
            while (atomicAdd(&g_flag[b * NCH + c], 0) == 0) __nanosleep(64);
            __threadfence();
        }
        __syncthreads();   // doubles as the post-compute barrier
    };
    auto prefetch_T = [&](int c, int buf) {
        const float* Tsrc = g_Tinv + (size_t)(b * NCH + c) * CC * CC;
        float* Tdst = Tb + buf * (CC * CC);
        for (int idx = tid; idx < CC * CC / 4; idx += 512)
            cp16cg(Tdst + idx * 4, Tsrc + idx * 4);
        if (tid < CC / 4)
            cp16cg(btb + buf * CC + tid * 4, g_beta + (size_t)(b * NCH + c) * CC + tid * 4);
    };

    prefetch_K(NCH - 1, (NCH - 1) & 1);
    wait_flag(NCH - 1);
    prefetch_T(NCH - 1, (NCH - 1) & 1);
    cp_commit();

    for (int c = NCH - 1; c >= 0; c--) {
        const int buf = c & 1;
        cp_wait0();
        __syncthreads();

        if (c > 0) prefetch_K(c - 1, buf ^ 1);   // flag-free, overlaps compute

        const float* K  = Kb + buf * (CC * HN);
        const float* Ti = Tb + buf * (CC * CC);
        const float* bt = btb + buf * CC;

        // step 1: m_j = K_j . u
        {
            const float4* K4 = reinterpret_cast<const float4*>(K);
            const float4* u4 = reinterpret_cast<const float4*>(us);
            int r0 = wid, r1 = wid + 16;
            float a0 = 0.f, a1 = 0.f;
            #pragma unroll
            for (int stp = 0; stp < 4; stp++) {
                int hb = stp * 32 + lane;
                float4 uv = u4[hb];
                float4 k0 = K4[r0 * 128 + hb];
                float4 k1 = K4[r1 * 128 + hb];
                a0 += k0.x * uv.x + k0.y * uv.y + k0.z * uv.z + k0.w * uv.w;
                a1 += k1.x * uv.x + k1.y * uv.y + k1.z * uv.z + k1.w * uv.w;
            }
            a0 = warp_sum(a0);
            a1 = warp_sum(a1);
            if (lane == 0) { ms[r0] = a0; ms[r1] = a1; }
        }
        __syncthreads();

        // step 2: s = Tinv * m ; sb = beta .* s
        {
            int r0 = wid, r1 = wid + 16;
            float mv = ms[lane];
            float a0 = Ti[r0 * CC + lane] * mv;
            float a1 = Ti[r1 * CC + lane] * mv;
            a0 = warp_sum(a0);
            a1 = warp_sum(a1);
            if (lane == 0) {
                ss[r0] = a0; sbs[r0] = a0 * bt[r0];
                ss[r1] = a1; sbs[r1] = a1 * bt[r1];
            }
        }
        __syncthreads();

        // step 3: u -= K^T sb ; ctx += K^T s
        {
            float ua = us[tid];
            #pragma unroll
            for (int j = 0; j < CC; j++) {
                float kv = K[j * HN + tid];
                ua   -= kv * sbs[j];
                racc += kv * ss[j];
            }
            us[tid] = ua;
        }
        // barrier folded into wait_flag below (c>0); not needed for c==0.

        if (c > 0) {
            wait_flag(c - 1);
            prefetch_T(c - 1, buf ^ 1);
            cp_commit();
        }
    }
    g_ctx[b * HN + tid] = racc;
}

// ---------------------------------------------------------------------------
// Phase C: out[b,i] = ctx[b,:] . W[i,:] + bias[i].
// grid (BN/8, 16): 8 batches per CTA to reuse W loads. Warp: 4 rows x 8 b.
// ---------------------------------------------------------------------------
__global__ void __launch_bounds__(256) out_kernel(const float* __restrict__ W,
                                                  const float* __restrict__ bias,
                                                  float* __restrict__ out) {
    __shared__ float cs[8][HN];
    const int b0 = blockIdx.x * 8;
    for (int i = threadIdx.x; i < 8 * HN; i += 256)
        cs[i >> 9][i & 511] = g_ctx[b0 * HN + i];
    __syncthreads();

    const int wid = threadIdx.x >> 5, lane = threadIdx.x & 31;
    const int row0 = blockIdx.y * 32 + wid * 4;

    float acc[4][8];
    #pragma unroll
    for (int r = 0; r < 4; r++)
        #pragma unroll
        for (int bb = 0; bb < 8; bb++) acc[r][bb] = 0.f;

    #pragma unroll
    for (int stp = 0; stp < 4; stp++) {
        int hb = stp * 32 + lane;
        float4 wv[4];
        #pragma unroll
        for (int r = 0; r < 4; r++)
            wv[r] = reinterpret_cast<const float4*>(W + (size_t)(row0 + r) * HN)[hb];
        #pragma unroll
        for (int bb = 0; bb < 8; bb++) {
            float4 cv = reinterpret_cast<const float4*>(cs[bb])[hb];
            #pragma unroll
            for (int r = 0; r < 4; r++)
                acc[r][bb] += wv[r].x * cv.x + wv[r].y * cv.y +
                              wv[r].z * cv.z + wv[r].w * cv.w;
        }
    }
    #pragma unroll
    for (int r = 0; r < 4; r++)
        #pragma unroll
        for (int bb = 0; bb < 8; bb++) {
            float v = warp_sum(acc[r][bb]);
            if (lane == 0) out[(b0 + bb) * HN + row0 + r] = v + bias[row0 + r];
        }
}

extern "C" void kernel_launch(void* const* d_in, const int* in_sizes, int n_in,
                              void* d_out, int out_size) {
    const float* hidden = (const float*)d_in[0];
    const float* W      = (const float*)d_in[1];
    const float* bias   = (const float*)d_in[2];
    float* out          = (float*)d_out;

    const int smA = (CC * HN + CC * GP + CC) * (int)sizeof(float);                  // ~68 KB
    const int smB = (2 * CC * HN + 2 * CC * CC + 2 * CC + HN + 3 * CC + SCAN_PAD)
                    * (int)sizeof(float);                                            // ~163 KB

    static cudaStream_t s2 = nullptr;
    static cudaEvent_t evA = nullptr, evB = nullptr;
    if (!s2) {
        int lo = 0, hi = 0;
        cudaDeviceGetStreamPriorityRange(&lo, &hi);
        cudaStreamCreateWithPriority(&s2, cudaStreamNonBlocking, hi);  // greatest prio
        cudaEventCreateWithFlags(&evA, cudaEventDisableTiming);
        cudaEventCreateWithFlags(&evB, cudaEventDisableTiming);
        cudaFuncSetAttribute(gram_kernel, cudaFuncAttributeMaxDynamicSharedMemorySize, smA);
        cudaFuncSetAttribute(scan_kernel, cudaFuncAttributeMaxDynamicSharedMemorySize, smB);
    }

    init_kernel<<<2, 1024>>>();
    cudaEventRecord(evA, 0);
    cudaStreamWaitEvent(s2, evA, 0);
    scan_kernel<<<BN, 512, smB, s2>>>(hidden);
    gram_kernel<<<dim3(BN, NCH), 256, smA>>>(hidden);
    cudaEventRecord(evB, s2);
    cudaStreamWaitEvent(0, evB, 0);
    out_kernel<<<dim3(BN / 8, 16), 256>>>(W, bias, out);
}

// round 6
// speedup vs baseline: 3.0502x; 1.1662x over previous
#include <cuda_runtime.h>
#include <cuda_bf16.h>
#include <cstdint>
#include <cstddef>

#define BN 32
#define LN 2048
#define TN 2047          // number of key timesteps (L-1)
#define HN 512
#define CC 32            // chunk size
#define NCH 64
#define NITEMS (BN * NCH)
#define EPSV 1e-6f
#define GP 33            // padded 32x32 stride
#define SCAN_PAD 6144

// Static device scratch
__device__ float g_Tinv[BN * NCH * CC * CC];   // 8 MB
__device__ float g_beta[BN * NCH * CC];
__device__ float g_ctx[BN * HN];
__device__ int   g_flag[BN * NCH];
__device__ int   g_ctr;

__device__ __forceinline__ float warp_sum(float v) {
    v += __shfl_xor_sync(0xffffffffu, v, 16);
    v += __shfl_xor_sync(0xffffffffu, v, 8);
    v += __shfl_xor_sync(0xffffffffu, v, 4);
    v += __shfl_xor_sync(0xffffffffu, v, 2);
    v += __shfl_xor_sync(0xffffffffu, v, 1);
    return v;
}

__device__ __forceinline__ void cp16cg(void* smem_dst, const void* gsrc) {
    unsigned sa = (unsigned)__cvta_generic_to_shared(smem_dst);
    asm volatile("cp.async.cg.shared.global [%0], [%1], 16;" :: "r"(sa), "l"(gsrc));
}
__device__ __forceinline__ void cp_commit() { asm volatile("cp.async.commit_group;"); }
__device__ __forceinline__ void cp_wait0()  { asm volatile("cp.async.wait_group 0;" ::: "memory"); }
__device__ __forceinline__ void cp_wait1()  { asm volatile("cp.async.wait_group 1;" ::: "memory"); }

__global__ void init_kernel() {
    int i = blockIdx.x * 1024 + threadIdx.x;
    if (i < NITEMS) g_flag[i] = 0;
    if (i == 0) g_ctr = 0;
}

// ---------------------------------------------------------------------------
// Phase A: persistent, pipelined gram. 116 CTAs x 512 threads, 1/SM.
// Work items level-major (level 63 first). Double-buffered 64KB tiles.
// ---------------------------------------------------------------------------
__global__ void __launch_bounds__(512) gram_kernel(const float* __restrict__ hidden) {
    extern __shared__ float sm[];
    float* K0    = sm;                     // 32*512
    float* K1    = sm + CC * HN;           // 32*512
    float* G     = sm + 2 * CC * HN;       // 32*33
    float* betas = G + CC * GP;            // 32
    __shared__ int sm_it;

    const int tid = threadIdx.x, wid = tid >> 5, lane = tid & 31;

    auto grab = [&]() -> int {
        if (tid == 0) sm_it = atomicAdd(&g_ctr, 1);
        __syncthreads();
        return sm_it;
    };
    auto prefetch = [&](int item, float* dst) {
        const int c = NCH - 1 - item / BN;
        const int b = item % BN;
        for (int idx = tid; idx < CC * (HN / 4); idx += 512) {
            int row = idx >> 7, col4 = idx & 127;
            int t = c * CC + (CC - 1) - row;
            float* dp = dst + row * HN + col4 * 4;
            if (t < TN) cp16cg(dp, hidden + (size_t)(b * LN + t) * HN + col4 * 4);
            else *reinterpret_cast<float4*>(dp) = make_float4(0.f, 0.f, 0.f, 0.f);
        }
    };

    int itA = grab();
    if (itA < NITEMS) prefetch(itA, K0);
    cp_commit();
    int pb = 0;

    while (itA < NITEMS) {
        int itB = grab();                       // contains a __syncthreads
        if (itB < NITEMS) prefetch(itB, pb ? K0 : K1);
        cp_commit();
        cp_wait1();                             // current tile ready (next may pend)
        __syncthreads();

        float4* Ks4 = reinterpret_cast<float4*>(pb ? K1 : K0);

        // Lower-triangular Gram: 36 4x4 blocks across 16 warps.
        for (int blk = wid; blk < 36; blk += 16) {
            int BI = 0, rem = blk;
            while (rem > BI) { BI++; rem -= BI; }
            int BJ = rem;

            float acc[4][4];
            #pragma unroll
            for (int i = 0; i < 4; i++)
                #pragma unroll
                for (int j = 0; j < 4; j++) acc[i][j] = 0.f;

            const float4* A4 = Ks4 + (4 * BI) * 128;
            const float4* B4 = Ks4 + (4 * BJ) * 128;
            #pragma unroll
            for (int stp = 0; stp < 4; stp++) {
                int hb = stp * 32 + lane;
                float4 av[4], bv[4];
                #pragma unroll
                for (int i = 0; i < 4; i++) av[i] = A4[i * 128 + hb];
                #pragma unroll
                for (int j = 0; j < 4; j++) bv[j] = B4[j * 128 + hb];
                #pragma unroll
                for (int i = 0; i < 4; i++)
                    #pragma unroll
                    for (int j = 0; j < 4; j++)
                        acc[i][j] += av[i].x * bv[j].x + av[i].y * bv[j].y +
                                     av[i].z * bv[j].z + av[i].w * bv[j].w;
            }
            #pragma unroll
            for (int i = 0; i < 4; i++)
                #pragma unroll
                for (int j = 0; j < 4; j++) {
                    float v = warp_sum(acc[i][j]);
                    if (lane == i * 4 + j) G[(4 * BI + i) * GP + (4 * BJ + j)] = v;
                }
        }
        __syncthreads();

        const int c = NCH - 1 - itA / BN;
        const int b = itA % BN;

        if (tid < CC) {
            float bt = 1.0f / (G[tid * GP + tid] + EPSV);
            betas[tid] = bt;
            g_beta[(b * NCH + c) * CC + tid] = bt;
        }
        __syncthreads();

        // Pre-scale L into G's upper-triangle slots: G[j][i] = G[i][j]*beta[j], j<i
        for (int e = tid; e < CC * CC; e += 512) {
            int i = e >> 5, j = e & 31;
            if (j < i) G[j * GP + i] = G[i * GP + j] * betas[j];
        }
        __syncthreads();

        // Register-resident unit-lower-triangular inverse (warp 0), col per lane.
        if (wid == 0) {
            float x[CC];
            float* Tout = g_Tinv + (size_t)(b * NCH + c) * CC * CC;
            #pragma unroll
            for (int i = 0; i < CC; i++) {
                float a0 = 0.f, a1 = 0.f;
                #pragma unroll
                for (int j = 0; j < CC; j++) {
                    if (j < i) {
                        float t = G[j * GP + i] * x[j];
                        if (j & 1) a1 -= t; else a0 -= t;
                    }
                }
                float xv = a0 + a1;
                x[i] = (i > lane) ? xv : ((i == lane) ? 1.f : 0.f);
                Tout[i * CC + lane] = x[i];
            }
            __syncwarp();
            __threadfence();
            if (lane == 0) atomicExch(&g_flag[b * NCH + c], 1);
        }
        __syncthreads();   // protect G/betas reuse next iteration

        itA = itB;
        pb ^= 1;
    }
}

// ---------------------------------------------------------------------------
// Phase B: backward chunked scan, concurrent with gram. Non-blocking flag
// probe at iteration top; blocking wait only if producer not yet ahead.
// grid BN, 512 threads.
// ---------------------------------------------------------------------------
__global__ void __launch_bounds__(512) scan_kernel(const float* __restrict__ hidden) {
    extern __shared__ float sm[];
    float* Kb  = sm;                       // 2 * CC * HN
    float* Tb  = sm + 2 * CC * HN;         // 2 * CC * CC
    float* btb = Tb + 2 * CC * CC;         // 2 * CC
    float* us  = btb + 2 * CC;             // HN
    float* ms  = us + HN;                  // CC
    float* ss  = ms + CC;                  // CC
    float* sbs = ss + CC;                  // CC
    int*   rdy = reinterpret_cast<int*>(sbs + CC);

    const int b = blockIdx.x;
    const int tid = threadIdx.x, wid = tid >> 5, lane = tid & 31;

    us[tid] = hidden[(size_t)(b * LN + (LN - 1)) * HN + tid];
    float racc = 0.f;

    const float* hb_base = hidden + (size_t)b * LN * HN;

    auto prefetch_K = [&](int c, int buf) {
        float* dstK = Kb + buf * (CC * HN);
        for (int idx = tid; idx < CC * (HN / 4); idx += 512) {
            int row = idx >> 7, col4 = idx & 127;
            int t = c * CC + (CC - 1) - row;
            float* dp = dstK + row * HN + col4 * 4;
            if (t < TN) cp16cg(dp, hb_base + (size_t)t * HN + col4 * 4);
            else *reinterpret_cast<float4*>(dp) = make_float4(0.f, 0.f, 0.f, 0.f);
        }
    };
    auto wait_flag = [&](int c) {
        if (tid == 0) {
            while (atomicAdd(&g_flag[b * NCH + c], 0) == 0) __nanosleep(64);
            __threadfence();
        }
        __syncthreads();
    };
    auto prefetch_T = [&](int c, int buf) {
        const float* Tsrc = g_Tinv + (size_t)(b * NCH + c) * CC * CC;
        float* Tdst = Tb + buf * (CC * CC);
        for (int idx = tid; idx < CC * CC / 4; idx += 512)
            cp16cg(Tdst + idx * 4, Tsrc + idx * 4);
        if (tid < CC / 4)
            cp16cg(btb + buf * CC + tid * 4, g_beta + (size_t)(b * NCH + c) * CC + tid * 4);
    };

    prefetch_K(NCH - 1, (NCH - 1) & 1);
    wait_flag(NCH - 1);
    prefetch_T(NCH - 1, (NCH - 1) & 1);
    cp_commit();

    for (int c = NCH - 1; c >= 0; c--) {
        const int buf = c & 1;
        cp_wait0();
        __syncthreads();

        if (c > 0) {
            prefetch_K(c - 1, buf ^ 1);   // flag-free, overlaps compute
            if (tid == 0) {
                int f = atomicAdd(&g_flag[b * NCH + (c - 1)], 0);
                if (f) __threadfence();
                *rdy = f;
            }
        }

        const float* K  = Kb + buf * (CC * HN);
        const float* Ti = Tb + buf * (CC * CC);
        const float* bt = btb + buf * CC;

        // step 1: m_j = K_j . u
        {
            const float4* K4 = reinterpret_cast<const float4*>(K);
            const float4* u4 = reinterpret_cast<const float4*>(us);
            int r0 = wid, r1 = wid + 16;
            float a0 = 0.f, a1 = 0.f;
            #pragma unroll
            for (int stp = 0; stp < 4; stp++) {
                int hb = stp * 32 + lane;
                float4 uv = u4[hb];
                float4 k0 = K4[r0 * 128 + hb];
                float4 k1 = K4[r1 * 128 + hb];
                a0 += k0.x * uv.x + k0.y * uv.y + k0.z * uv.z + k0.w * uv.w;
                a1 += k1.x * uv.x + k1.y * uv.y + k1.z * uv.z + k1.w * uv.w;
            }
            a0 = warp_sum(a0);
            a1 = warp_sum(a1);
            if (lane == 0) { ms[r0] = a0; ms[r1] = a1; }
        }
        __syncthreads();

        // step 2: s = Tinv * m ; sb = beta .* s
        {
            int r0 = wid, r1 = wid + 16;
            float mv = ms[lane];
            float a0 = Ti[r0 * CC + lane] * mv;
            float a1 = Ti[r1 * CC + lane] * mv;
            a0 = warp_sum(a0);
            a1 = warp_sum(a1);
            if (lane == 0) {
                ss[r0] = a0; sbs[r0] = a0 * bt[r0];
                ss[r1] = a1; sbs[r1] = a1 * bt[r1];
            }
        }
        __syncthreads();

        // step 3: u -= K^T sb ; ctx += K^T s
        {
            float ua = us[tid];
            #pragma unroll
            for (int j = 0; j < CC; j++) {
                float kv = K[j * HN + tid];
                ua   -= kv * sbs[j];
                racc += kv * ss[j];
            }
            us[tid] = ua;
        }

        if (c > 0) {
            if (*rdy) {
                // producer already ahead: fetch Tinv without blocking wait
                prefetch_T(c - 1, buf ^ 1);
                cp_commit();
            } else {
                wait_flag(c - 1);          // includes the needed barrier
                prefetch_T(c - 1, buf ^ 1);
                cp_commit();
            }
        }
    }
    g_ctx[b * HN + tid] = racc;
}

// ---------------------------------------------------------------------------
// Phase C (R4 version): out[b,i] = ctx[b,:] . W[i,:] + bias[i].
// grid (BN, 8), 256 threads; each warp does 8 rows with 8-way load MLP.
// ---------------------------------------------------------------------------
__global__ void __launch_bounds__(256) out_kernel(const float* __restrict__ W,
                                                  const float* __restrict__ bias,
                                                  float* __restrict__ out) {
    __shared__ float cs[HN];
    const int b = blockIdx.x;
    for (int i = threadIdx.x; i < HN; i += 256) cs[i] = g_ctx[b * HN + i];
    __syncthreads();

    const int wid = threadIdx.x >> 5, lane = threadIdx.x & 31;
    const int row0 = blockIdx.y * 64 + wid * 8;
    const float4* c4 = reinterpret_cast<const float4*>(cs);

    float acc[8];
    #pragma unroll
    for (int r = 0; r < 8; r++) acc[r] = 0.f;

    #pragma unroll
    for (int stp = 0; stp < 4; stp++) {
        int hb = stp * 32 + lane;
        float4 cv = c4[hb];
        #pragma unroll
        for (int r = 0; r < 8; r++) {
            float4 wv = reinterpret_cast<const float4*>(W + (size_t)(row0 + r) * HN)[hb];
            acc[r] += wv.x * cv.x + wv.y * cv.y + wv.z * cv.z + wv.w * cv.w;
        }
    }
    #pragma unroll
    for (int r = 0; r < 8; r++) {
        float v = warp_sum(acc[r]);
        if (lane == 0) out[b * HN + row0 + r] = v + bias[row0 + r];
    }
}

extern "C" void kernel_launch(void* const* d_in, const int* in_sizes, int n_in,
                              void* d_out, int out_size) {
    const float* hidden = (const float*)d_in[0];
    const float* W      = (const float*)d_in[1];
    const float* bias   = (const float*)d_in[2];
    float* out          = (float*)d_out;

    const int smA = (2 * CC * HN + CC * GP + CC + 8) * (int)sizeof(float);          // ~136 KB
    const int smB = (2 * CC * HN + 2 * CC * CC + 2 * CC + HN + 3 * CC + 8 + SCAN_PAD)
                    * (int)sizeof(float);                                            // ~163 KB

    static cudaStream_t s2 = nullptr;
    static cudaEvent_t evA = nullptr, evB = nullptr;
    if (!s2) {
        int lo = 0, hi = 0;
        cudaDeviceGetStreamPriorityRange(&lo, &hi);
        cudaStreamCreateWithPriority(&s2, cudaStreamNonBlocking, hi);
        cudaEventCreateWithFlags(&evA, cudaEventDisableTiming);
        cudaEventCreateWithFlags(&evB, cudaEventDisableTiming);
        cudaFuncSetAttribute(gram_kernel, cudaFuncAttributeMaxDynamicSharedMemorySize, smA);
        cudaFuncSetAttribute(scan_kernel, cudaFuncAttributeMaxDynamicSharedMemorySize, smB);
    }

    init_kernel<<<2, 1024>>>();
    cudaEventRecord(evA, 0);
    cudaStreamWaitEvent(s2, evA, 0);
    scan_kernel<<<BN, 512, smB, s2>>>(hidden);
    gram_kernel<<<116, 512, smA>>>(hidden);
    cudaEventRecord(evB, s2);
    cudaStreamWaitEvent(0, evB, 0);
    out_kernel<<<dim3(BN, 8), 256>>>(W, bias, out);
}

// round 7
// speedup vs baseline: 3.6921x; 1.2104x over previous
#include <cuda_runtime.h>
#include <cuda_bf16.h>
#include <cstdint>
#include <cstddef>

#define BN 32
#define LN 2048
#define TN 2047          // number of key timesteps (L-1)
#define HN 512
#define CC 32            // chunk size
#define NCH 64
#define NITEMS (BN * NCH)
#define EPSV 1e-6f
#define GP 33            // padded 32x32 stride

// Static device scratch
__device__ float g_Tinv[BN * NCH * CC * CC];   // 8 MB
__device__ float g_beta[BN * NCH * CC];
__device__ float g_ctx[BN * HN];
__device__ int   g_flag[BN * NCH];
__device__ int   g_ctr;

__device__ __forceinline__ float warp_sum(float v) {
    v += __shfl_xor_sync(0xffffffffu, v, 16);
    v += __shfl_xor_sync(0xffffffffu, v, 8);
    v += __shfl_xor_sync(0xffffffffu, v, 4);
    v += __shfl_xor_sync(0xffffffffu, v, 2);
    v += __shfl_xor_sync(0xffffffffu, v, 1);
    return v;
}

__device__ __forceinline__ void cp16cg(void* smem_dst, const void* gsrc) {
    unsigned sa = (unsigned)__cvta_generic_to_shared(smem_dst);
    asm volatile("cp.async.cg.shared.global [%0], [%1], 16;" :: "r"(sa), "l"(gsrc));
}
__device__ __forceinline__ void cp_commit() { asm volatile("cp.async.commit_group;"); }
__device__ __forceinline__ void cp_wait0()  { asm volatile("cp.async.wait_group 0;" ::: "memory"); }
__device__ __forceinline__ void cp_wait1()  { asm volatile("cp.async.wait_group 1;" ::: "memory"); }

__global__ void init_kernel() {
    int i = blockIdx.x * 1024 + threadIdx.x;
    if (i < NITEMS) g_flag[i] = 0;
    if (i == 0) g_ctr = 0;
}

// ---------------------------------------------------------------------------
// Phase A (unchanged from R6): persistent, pipelined gram. 116 CTAs x 512 thr.
// ---------------------------------------------------------------------------
__global__ void __launch_bounds__(512) gram_kernel(const float* __restrict__ hidden) {
    extern __shared__ float sm[];
    float* K0    = sm;                     // 32*512
    float* K1    = sm + CC * HN;           // 32*512
    float* G     = sm + 2 * CC * HN;       // 32*33
    float* betas = G + CC * GP;            // 32
    __shared__ int sm_it;

    const int tid = threadIdx.x, wid = tid >> 5, lane = tid & 31;

    auto grab = [&]() -> int {
        if (tid == 0) sm_it = atomicAdd(&g_ctr, 1);
        __syncthreads();
        return sm_it;
    };
    auto prefetch = [&](int item, float* dst) {
        const int c = NCH - 1 - item / BN;
        const int b = item % BN;
        for (int idx = tid; idx < CC * (HN / 4); idx += 512) {
            int row = idx >> 7, col4 = idx & 127;
            int t = c * CC + (CC - 1) - row;
            float* dp = dst + row * HN + col4 * 4;
            if (t < TN) cp16cg(dp, hidden + (size_t)(b * LN + t) * HN + col4 * 4);
            else *reinterpret_cast<float4*>(dp) = make_float4(0.f, 0.f, 0.f, 0.f);
        }
    };

    int itA = grab();
    if (itA < NITEMS) prefetch(itA, K0);
    cp_commit();
    int pb = 0;

    while (itA < NITEMS) {
        int itB = grab();
        if (itB < NITEMS) prefetch(itB, pb ? K0 : K1);
        cp_commit();
        cp_wait1();
        __syncthreads();

        float4* Ks4 = reinterpret_cast<float4*>(pb ? K1 : K0);

        for (int blk = wid; blk < 36; blk += 16) {
            int BI = 0, rem = blk;
            while (rem > BI) { BI++; rem -= BI; }
            int BJ = rem;

            float acc[4][4];
            #pragma unroll
            for (int i = 0; i < 4; i++)
                #pragma unroll
                for (int j = 0; j < 4; j++) acc[i][j] = 0.f;

            const float4* A4 = Ks4 + (4 * BI) * 128;
            const float4* B4 = Ks4 + (4 * BJ) * 128;
            #pragma unroll
            for (int stp = 0; stp < 4; stp++) {
                int hb = stp * 32 + lane;
                float4 av[4], bv[4];
                #pragma unroll
                for (int i = 0; i < 4; i++) av[i] = A4[i * 128 + hb];
                #pragma unroll
                for (int j = 0; j < 4; j++) bv[j] = B4[j * 128 + hb];
                #pragma unroll
                for (int i = 0; i < 4; i++)
                    #pragma unroll
                    for (int j = 0; j < 4; j++)
                        acc[i][j] += av[i].x * bv[j].x + av[i].y * bv[j].y +
                                     av[i].z * bv[j].z + av[i].w * bv[j].w;
            }
            #pragma unroll
            for (int i = 0; i < 4; i++)
                #pragma unroll
                for (int j = 0; j < 4; j++) {
                    float v = warp_sum(acc[i][j]);
                    if (lane == i * 4 + j) G[(4 * BI + i) * GP + (4 * BJ + j)] = v;
                }
        }
        __syncthreads();

        const int c = NCH - 1 - itA / BN;
        const int b = itA % BN;

        if (tid < CC) {
            float bt = 1.0f / (G[tid * GP + tid] + EPSV);
            betas[tid] = bt;
            g_beta[(b * NCH + c) * CC + tid] = bt;
        }
        __syncthreads();

        for (int e = tid; e < CC * CC; e += 512) {
            int i = e >> 5, j = e & 31;
            if (j < i) G[j * GP + i] = G[i * GP + j] * betas[j];
        }
        __syncthreads();

        if (wid == 0) {
            float x[CC];
            float* Tout = g_Tinv + (size_t)(b * NCH + c) * CC * CC;
            #pragma unroll
            for (int i = 0; i < CC; i++) {
                float a0 = 0.f, a1 = 0.f;
                #pragma unroll
                for (int j = 0; j < CC; j++) {
                    if (j < i) {
                        float t = G[j * GP + i] * x[j];
                        if (j & 1) a1 -= t; else a0 -= t;
                    }
                }
                float xv = a0 + a1;
                x[i] = (i > lane) ? xv : ((i == lane) ? 1.f : 0.f);
                Tout[i * CC + lane] = x[i];
            }
            __syncwarp();
            __threadfence();
            if (lane == 0) atomicExch(&g_flag[b * NCH + c], 1);
        }
        __syncthreads();

        itA = itB;
        pb ^= 1;
    }
}

// ---------------------------------------------------------------------------
// Phase B v3: register-resident backward scan. grid BN, 512 threads.
// Thread tid owns H-column tid: u and K columns live in registers.
// Only Tinv/beta use smem (cp.async double-buffered, flag-gated).
// ---------------------------------------------------------------------------
__global__ void __launch_bounds__(512) scan_kernel(const float* __restrict__ hidden) {
    extern __shared__ float sm[];
    float*  Tb   = sm;                     // 2 * 32*32
    float*  btb  = Tb + 2 * CC * CC;       // 2 * 32
    float*  part = btb + 2 * CC;           // 16 * 33
    float*  ms   = part + 16 * 33;         // 32
    float2* ssb  = reinterpret_cast<float2*>(ms + CC);  // 32 float2
    int*    rdy  = reinterpret_cast<int*>(ssb + CC);

    const int b = blockIdx.x;
    const int tid = threadIdx.x, wid = tid >> 5, lane = tid & 31;
    const float* hb = hidden + (size_t)b * LN * HN;

    float u = hb[(size_t)(LN - 1) * HN + tid];
    float racc = 0.f;

    float KA[CC], KB[CC];

    auto loadK = [&](int c, float (&Kr)[CC]) {
        #pragma unroll
        for (int j = 0; j < CC; j++) {
            int t = c * CC + (CC - 1) - j;
            Kr[j] = (t < TN) ? hb[(size_t)t * HN + tid] : 0.f;
        }
    };
    auto wait_flag = [&](int c) {
        if (tid == 0) {
            while (atomicAdd(&g_flag[b * NCH + c], 0) == 0) __nanosleep(64);
            __threadfence();
        }
        __syncthreads();
    };
    auto prefetch_T = [&](int c, int buf) {
        const float* Tsrc = g_Tinv + (size_t)(b * NCH + c) * CC * CC;
        float* Tdst = Tb + buf * (CC * CC);
        if (tid < CC * CC / 4)
            cp16cg(Tdst + tid * 4, Tsrc + tid * 4);
        else if (tid < CC * CC / 4 + CC / 4) {
            int q = tid - CC * CC / 4;
            cp16cg(btb + buf * CC + q * 4, g_beta + (size_t)(b * NCH + c) * CC + q * 4);
        }
        cp_commit();
    };

    auto chunk_body = [&](int c, const float (&K)[CC]) {
        const int buf = c & 1;
        // non-blocking probe for next chunk's flag (read after step 3)
        if (c > 0 && tid == 0) {
            int f = atomicAdd(&g_flag[b * NCH + (c - 1)], 0);
            if (f) __threadfence();
            *rdy = f;
        }

        // step 1: fused multiply + butterfly transpose-reduce.
        // After 5 rounds, t[0] = sum over this warp's 32 lanes of K[lane-idx]... -> m_partial[lane]
        float t[16];
        {
            const bool h16 = (lane & 16) != 0;
            #pragma unroll
            for (int j = 0; j < 16; j++) {
                float give = (h16 ? K[j] : K[j + 16]) * u;
                float keep = (h16 ? K[j + 16] : K[j]) * u;
                t[j] = keep + __shfl_xor_sync(0xffffffffu, give, 16);
            }
            const bool h8 = (lane & 8) != 0;
            #pragma unroll
            for (int j = 0; j < 8; j++) {
                float give = h8 ? t[j] : t[j + 8];
                float keep = h8 ? t[j + 8] : t[j];
                t[j] = keep + __shfl_xor_sync(0xffffffffu, give, 8);
            }
            const bool h4 = (lane & 4) != 0;
            #pragma unroll
            for (int j = 0; j < 4; j++) {
                float give = h4 ? t[j] : t[j + 4];
                float keep = h4 ? t[j + 4] : t[j];
                t[j] = keep + __shfl_xor_sync(0xffffffffu, give, 4);
            }
            const bool h2 = (lane & 2) != 0;
            #pragma unroll
            for (int j = 0; j < 2; j++) {
                float give = h2 ? t[j] : t[j + 2];
                float keep = h2 ? t[j + 2] : t[j];
                t[j] = keep + __shfl_xor_sync(0xffffffffu, give, 2);
            }
            {
                const bool h1 = (lane & 1) != 0;
                float give = h1 ? t[0] : t[1];
                float keep = h1 ? t[1] : t[0];
                t[0] = keep + __shfl_xor_sync(0xffffffffu, give, 1);
            }
            part[wid * 33 + lane] = t[0];
        }
        cp_wait0();          // T(c) copy done (each thread's own group)
        __syncthreads();     // B1: part + Tb/btb visible

        // warp 0: combine 16 warp partials -> m
        if (wid == 0) {
            float mm = 0.f;
            #pragma unroll
            for (int w = 0; w < 16; w++) mm += part[w * 33 + lane];
            ms[lane] = mm;
        }
        __syncthreads();     // B2: ms visible

        // step 2: s = Tinv * m ; store (s, beta*s) as float2
        {
            const float* Ti = Tb + buf * (CC * CC);
            const float* bt = btb + buf * CC;
            int r0 = wid, r1 = wid + 16;
            float mv = ms[lane];
            float a0 = Ti[r0 * CC + lane] * mv;
            float a1 = Ti[r1 * CC + lane] * mv;
            a0 = warp_sum(a0);
            a1 = warp_sum(a1);
            if (lane == 0) {
                ssb[r0] = make_float2(a0, a0 * bt[r0]);
                ssb[r1] = make_float2(a1, a1 * bt[r1]);
            }
        }
        __syncthreads();     // B3: ssb visible

        // step 3: u -= K^T sb ; ctx += K^T s (all registers + broadcast LDS)
        #pragma unroll
        for (int j = 0; j < CC; j++) {
            float2 sv = ssb[j];
            racc += K[j] * sv.x;
            u    -= K[j] * sv.y;
        }

        // fetch next chunk's Tinv/beta
        if (c > 0) {
            if (*rdy) {
                prefetch_T(c - 1, buf ^ 1);
            } else {
                wait_flag(c - 1);
                prefetch_T(c - 1, buf ^ 1);
            }
        }
    };

    // prologue: chunk 63
    loadK(NCH - 1, KA);
    wait_flag(NCH - 1);
    prefetch_T(NCH - 1, (NCH - 1) & 1);

    // 2x-unrolled main loop with register double-buffering (NCH even)
    for (int c = NCH - 1; c >= 1; c -= 2) {
        loadK(c - 1, KB);
        chunk_body(c, KA);
        if (c - 2 >= 0) loadK(c - 2, KA);
        chunk_body(c - 1, KB);
    }

    g_ctx[b * HN + tid] = racc;
}

// ---------------------------------------------------------------------------
// Phase C (R4 version): out[b,i] = ctx[b,:] . W[i,:] + bias[i].
// ---------------------------------------------------------------------------
__global__ void __launch_bounds__(256) out_kernel(const float* __restrict__ W,
                                                  const float* __restrict__ bias,
                                                  float* __restrict__ out) {
    __shared__ float cs[HN];
    const int b = blockIdx.x;
    for (int i = threadIdx.x; i < HN; i += 256) cs[i] = g_ctx[b * HN + i];
    __syncthreads();

    const int wid = threadIdx.x >> 5, lane = threadIdx.x & 31;
    const int row0 = blockIdx.y * 64 + wid * 8;
    const float4* c4 = reinterpret_cast<const float4*>(cs);

    float acc[8];
    #pragma unroll
    for (int r = 0; r < 8; r++) acc[r] = 0.f;

    #pragma unroll
    for (int stp = 0; stp < 4; stp++) {
        int hb = stp * 32 + lane;
        float4 cv = c4[hb];
        #pragma unroll
        for (int r = 0; r < 8; r++) {
            float4 wv = reinterpret_cast<const float4*>(W + (size_t)(row0 + r) * HN)[hb];
            acc[r] += wv.x * cv.x + wv.y * cv.y + wv.z * cv.z + wv.w * cv.w;
        }
    }
    #pragma unroll
    for (int r = 0; r < 8; r++) {
        float v = warp_sum(acc[r]);
        if (lane == 0) out[b * HN + row0 + r] = v + bias[row0 + r];
    }
}

extern "C" void kernel_launch(void* const* d_in, const int* in_sizes, int n_in,
                              void* d_out, int out_size) {
    const float* hidden = (const float*)d_in[0];
    const float* W      = (const float*)d_in[1];
    const float* bias   = (const float*)d_in[2];
    float* out          = (float*)d_out;

    const int smA = (2 * CC * HN + CC * GP + CC + 8) * (int)sizeof(float);  // ~136 KB
    const int smB = 100 * 1024;  // real usage ~12 KB; padded to evict gram from scan SMs

    static cudaStream_t s2 = nullptr;
    static cudaEvent_t evA = nullptr, evB = nullptr;
    if (!s2) {
        int lo = 0, hi = 0;
        cudaDeviceGetStreamPriorityRange(&lo, &hi);
        cudaStreamCreateWithPriority(&s2, cudaStreamNonBlocking, hi);
        cudaEventCreateWithFlags(&evA, cudaEventDisableTiming);
        cudaEventCreateWithFlags(&evB, cudaEventDisableTiming);
        cudaFuncSetAttribute(gram_kernel, cudaFuncAttributeMaxDynamicSharedMemorySize, smA);
        cudaFuncSetAttribute(scan_kernel, cudaFuncAttributeMaxDynamicSharedMemorySize, smB);
    }

    init_kernel<<<2, 1024>>>();
    cudaEventRecord(evA, 0);
    cudaStreamWaitEvent(s2, evA, 0);
    scan_kernel<<<BN, 512, smB, s2>>>(hidden);
    gram_kernel<<<116, 512, smA>>>(hidden);
    cudaEventRecord(evB, s2);
    cudaStreamWaitEvent(0, evB, 0);
    out_kernel<<<dim3(BN, 8), 256>>>(W, bias, out);
}